// round 15
// baseline (speedup 1.0000x reference)
#include <cuda_runtime.h>

// ---------------------------------------------------------------------------
// 2-layer LSTM (H=512) encode (T=1024) + AR decode (64 outputs), batch row 255
// only (the reference output depends only on that row).
//
// DATAFLOW version: NO grid barrier, NO fences, NO atomics. Every h-component
// is published as one 8-byte relaxed-atomic word  (tag<<32 | float_bits)  in a
// depth-8 ring. Consumers spin on the tags of the exact step they need; the
// poll IS the data load (tag+value arrive in one atomic word, so no
// release/acquire pairing is required). Warps are independent dataflow actors.
//
// 128 CTAs x 256 threads = 1024 warps, types mixed per CTA (SMSP balance):
//   warps 0..3: type-1 (layer-1 cell), k = 4*bid + w      (Whh1 rows in regs)
//   warps 4..7: type-2 (layer-2 cell), k = 4*bid + (w-4)  (Whh2+Wih2 in regs)
//
// Tag convention: value h*[s] carries tag s+1 and lives in ring slot (s+1)&7.
// Ring overwrite safety (depth 8):
//  - consuming the FULL previous vector proves every peer warp advanced
//    (self-chain), and
//  - type-1 in encode additionally checks h2 tags >= t-7 (monotonic
//    back-pressure) before overwriting h1[t-8], bounding type-2's lag.
// Ordering relies only on (1) 8B relaxed single-copy atomicity and (2) stores
// not issuing before the data-dependent poll branch resolves (no store
// speculation on GPU).
// ---------------------------------------------------------------------------

typedef unsigned long long ull;

#define GRID   128
#define TPB    256
#define HH     512
#define T_ENC  1024
#define PRED   64
#define DQ     8

// ---- persistent rings (reset by init kernel every launch) -------------------
__device__ __align__(16) ull g_h1r[DQ][HH];
__device__ __align__(16) ull g_h2r[DQ][HH];

__global__ void lstm_init_kernel() {
    for (int j = threadIdx.x; j < DQ * HH; j += blockDim.x) {
        ((ull*)g_h1r)[j] = 0ull;   // tag 0 = h[-1] = 0.0f
        ((ull*)g_h2r)[j] = 0ull;
    }
}

// ---- relaxed 8B atomics ------------------------------------------------------
__device__ __forceinline__ ull ld_rlx(const ull* p) {
    ull v;
    asm volatile("ld.relaxed.gpu.u64 %0, [%1];" : "=l"(v) : "l"(p) : "memory");
    return v;
}
__device__ __forceinline__ void st_tag(ull* p, unsigned tag, float val) {
    ull v = ((ull)tag << 32) | (ull)__float_as_uint(val);
    asm volatile("st.relaxed.gpu.u64 [%0], %1;" :: "l"(p), "l"(v) : "memory");
}

// Poll ring slot until ALL 512 tags == want; returns the 16 floats this lane
// owns (elements lane + 32*j). Retries reload ONLY stale entries.
__device__ __forceinline__ void poll_eq(const ull* slot, unsigned want,
                                        float h[16], int lane) {
    ull v[16];
#pragma unroll
    for (int j = 0; j < 16; ++j) v[j] = ld_rlx(&slot[lane + 32 * j]);
    while (true) {
        bool mine = true;
#pragma unroll
        for (int j = 0; j < 16; ++j) mine &= ((unsigned)(v[j] >> 32) == want);
        if (__all_sync(0xffffffffu, mine)) break;
#pragma unroll
        for (int j = 0; j < 16; ++j)
            if ((unsigned)(v[j] >> 32) != want) v[j] = ld_rlx(&slot[lane + 32 * j]);
    }
#pragma unroll
    for (int j = 0; j < 16; ++j) h[j] = __uint_as_float((unsigned)v[j]);
}

// Back-pressure: wait until ALL tags in slot >= want (monotonic; data unused).
__device__ __forceinline__ void poll_ge(const ull* slot, unsigned want, int lane) {
    bool ok;
    do {
        bool mine = true;
#pragma unroll
        for (int j = 0; j < 16; ++j) {
            ull v = ld_rlx(&slot[lane + 32 * j]);
            mine &= ((unsigned)(v >> 32) >= want);
        }
        ok = __all_sync(0xffffffffu, mine);
    } while (!ok);
}

// ---- math helpers ------------------------------------------------------------
__device__ __forceinline__ float warp_sum(float s) {
#pragma unroll
    for (int o = 16; o; o >>= 1) s += __shfl_xor_sync(0xffffffffu, s, o);
    return s;
}

__device__ __forceinline__ void mv4(const float w[4][16], const float h[16], float s[4]) {
#pragma unroll
    for (int g = 0; g < 4; ++g) {
        float a = 0.f;
#pragma unroll
        for (int j = 0; j < 16; ++j) a = fmaf(w[g][j], h[j], a);
        s[g] = a;
    }
#pragma unroll
    for (int o = 16; o; o >>= 1)
#pragma unroll
        for (int g = 0; g < 4; ++g) s[g] += __shfl_xor_sync(0xffffffffu, s[g], o);
}

__device__ __forceinline__ void mv8(const float wa[4][16], const float ha[16],
                                    const float wb[4][16], const float hb[16],
                                    float s[8]) {
#pragma unroll
    for (int g = 0; g < 4; ++g) {
        float a = 0.f, b = 0.f;
#pragma unroll
        for (int j = 0; j < 16; ++j) {
            a = fmaf(wa[g][j], ha[j], a);
            b = fmaf(wb[g][j], hb[j], b);
        }
        s[g] = a; s[4 + g] = b;
    }
#pragma unroll
    for (int o = 16; o; o >>= 1)
#pragma unroll
        for (int g = 0; g < 8; ++g) s[g] += __shfl_xor_sync(0xffffffffu, s[g], o);
}

__device__ __forceinline__ float sigf(float x) { return 1.f / (1.f + __expf(-x)); }

__device__ __forceinline__ float cellf(float pi, float pf, float pg, float po, float& c) {
    float i_ = sigf(pi), f_ = sigf(pf), g_ = tanhf(pg), o_ = sigf(po);
    c = f_ * c + i_ * g_;
    return o_ * tanhf(c);
}

// ---- main persistent kernel ----------------------------------------------------
__global__ void __launch_bounds__(TPB, 1) lstm_main_kernel(
    const float* __restrict__ input,
    const float* __restrict__ Wih1, const float* __restrict__ Whh1,
    const float* __restrict__ bih1, const float* __restrict__ bhh1,
    const float* __restrict__ Wih2, const float* __restrict__ Whh2,
    const float* __restrict__ bih2, const float* __restrict__ bhh2,
    const float* __restrict__ Wlin, const float* __restrict__ blin,
    float* __restrict__ out)
{
    const int  lane = threadIdx.x & 31;
    const int  bid  = blockIdx.x;
    const int  wid  = threadIdx.x >> 5;        // 0..7
    const bool is1  = (wid < 4);
    const int  k    = bid * 4 + (wid & 3);     // 0..511 per type

    // ---- one-time: this warp's weight rows -> REGISTERS ----
    // Element->lane mapping matches the ring: element index = lane + 32*j.
    float wA[4][16], wB[4][16], wlin[16];
    {
        const float* WA = is1 ? Whh1 : Whh2;
#pragma unroll
        for (int g = 0; g < 4; ++g) {
            const float* row = WA + (size_t)(k + 512 * g) * HH;
#pragma unroll
            for (int j = 0; j < 16; ++j) wA[g][j] = __ldg(&row[lane + 32 * j]);
        }
        if (!is1) {
#pragma unroll
            for (int g = 0; g < 4; ++g) {
                const float* row = Wih2 + (size_t)(k + 512 * g) * HH;
#pragma unroll
                for (int j = 0; j < 16; ++j) wB[g][j] = __ldg(&row[lane + 32 * j]);
            }
        } else {
#pragma unroll
            for (int g = 0; g < 4; ++g)
#pragma unroll
                for (int j = 0; j < 16; ++j) wB[g][j] = 0.f;
        }
#pragma unroll
        for (int j = 0; j < 16; ++j) wlin[j] = __ldg(&Wlin[lane + 32 * j]);
    }
    float bsum[4], wx[4];
#pragma unroll
    for (int g = 0; g < 4; ++g) {
        int r = k + 512 * g;
        if (is1) { bsum[g] = __ldg(&bih1[r]) + __ldg(&bhh1[r]); wx[g] = __ldg(&Wih1[r]); }
        else     { bsum[g] = __ldg(&bih2[r]) + __ldg(&bhh2[r]); wx[g] = 0.f; }
    }
    const float blin0 = __ldg(blin);

    float cs = 0.f;   // c1 (type-1) or c2 (type-2); lane 0 of this warp

    // ================= ENCODE (dataflow; layer-2 lags one step) ==============
    if (is1) {
        for (int t = 0; t < T_ENC; ++t) {
            // back-pressure: before overwriting h1[t-8], ensure all type-2
            // warps finished interval t-7 (produced h2[t-8], tag t-7).
            if (t >= 7) poll_ge(g_h2r[(unsigned)(t - 7) & 7], (unsigned)(t - 7), lane);
            float h[16];
            poll_eq(g_h1r[t & 7], (unsigned)t, h, lane);          // h1[t-1]
            float x = __ldg(&input[255 * T_ENC + t]);
            float s[4];
            mv4(wA, h, s);
            if (lane == 0) {
                float hn = cellf(s[0] + bsum[0] + wx[0] * x,
                                 s[1] + bsum[1] + wx[1] * x,
                                 s[2] + bsum[2] + wx[2] * x,
                                 s[3] + bsum[3] + wx[3] * x, cs);
                st_tag(&g_h1r[(t + 1) & 7][k], (unsigned)(t + 1), hn);  // h1[t]
            }
        }
    } else {
        for (int t = 1; t < T_ENC; ++t) {
            float h2v[16], h1v[16];
            poll_eq(g_h2r[(t - 1) & 7], (unsigned)(t - 1), h2v, lane); // h2[t-2]
            poll_eq(g_h1r[t & 7],       (unsigned)t,       h1v, lane); // h1[t-1]
            float s[8];
            mv8(wA, h2v, wB, h1v, s);
            if (lane == 0) {
                float hn = cellf(s[0] + s[4] + bsum[0],
                                 s[1] + s[5] + bsum[1],
                                 s[2] + s[6] + bsum[2],
                                 s[3] + s[7] + bsum[3], cs);
                st_tag(&g_h2r[t & 7][k], (unsigned)t, hn);             // h2[t-1]
            }
        }
        // ---- drain: produce h2[1023] ----
        {
            float h2v[16], h1v[16];
            poll_eq(g_h2r[(T_ENC - 1) & 7], (unsigned)(T_ENC - 1), h2v, lane); // h2[1022]
            poll_eq(g_h1r[T_ENC & 7],       (unsigned)T_ENC,       h1v, lane); // h1[1023]
            float s[8];
            mv8(wA, h2v, wB, h1v, s);
            if (lane == 0) {
                float hn = cellf(s[0] + s[4] + bsum[0],
                                 s[1] + s[5] + bsum[1],
                                 s[2] + s[6] + bsum[2],
                                 s[3] + s[7] + bsum[3], cs);
                st_tag(&g_h2r[T_ENC & 7][k], (unsigned)T_ENC, hn);             // h2[1023]
            }
        }
    }

    // ================= AR DECODE: t = 1024 .. 1086 (dataflow) =================
    for (int t = T_ENC; t < T_ENC + PRED - 1; ++t) {
        if (is1) {
            float h2v[16];
            poll_eq(g_h2r[t & 7], (unsigned)t, h2v, lane);        // h2[t-1]
            float y = 0.f;
#pragma unroll
            for (int j = 0; j < 16; ++j) y = fmaf(wlin[j], h2v[j], y);
            y = warp_sum(y) + blin0;
            if (k == 0 && lane == 0) out[t - T_ENC] = y;          // out[0..62]
            float x = y;   // bitwise identical in all type-1 warps (same words read)
            float h[16];
            poll_eq(g_h1r[t & 7], (unsigned)t, h, lane);          // h1[t-1]
            float s[4];
            mv4(wA, h, s);
            if (lane == 0) {
                float hn = cellf(s[0] + bsum[0] + wx[0] * x,
                                 s[1] + bsum[1] + wx[1] * x,
                                 s[2] + bsum[2] + wx[2] * x,
                                 s[3] + bsum[3] + wx[3] * x, cs);
                st_tag(&g_h1r[(t + 1) & 7][k], (unsigned)(t + 1), hn);  // h1[t]
            }
        } else {
            float h2v[16], h1v[16];
            poll_eq(g_h2r[t & 7],       (unsigned)t,       h2v, lane); // h2[t-1]
            poll_eq(g_h1r[(t + 1) & 7], (unsigned)(t + 1), h1v, lane); // h1[t]
            float s[8];
            mv8(wA, h2v, wB, h1v, s);
            if (lane == 0) {
                float hn = cellf(s[0] + s[4] + bsum[0],
                                 s[1] + s[5] + bsum[1],
                                 s[2] + s[6] + bsum[2],
                                 s[3] + s[7] + bsum[3], cs);
                st_tag(&g_h2r[(t + 1) & 7][k], (unsigned)(t + 1), hn);  // h2[t]
            }
        }
    }

    // ================= EPILOGUE: out[63] = Wlin . h2[1086] + blin ==============
    if (bid == 0 && wid == 0) {
        float h2v[16];
        poll_eq(g_h2r[(T_ENC + PRED - 1) & 7], (unsigned)(T_ENC + PRED - 1),
                h2v, lane);                                        // h2[1086], tag 1087
        float y = 0.f;
#pragma unroll
        for (int j = 0; j < 16; ++j) y = fmaf(wlin[j], h2v[j], y);
        y = warp_sum(y) + blin0;
        if (lane == 0) out[PRED - 1] = y;
    }
}

// ---------------------------------------------------------------------------
// inputs (metadata order): 0 input(256x1024 f32), 1 pred_len(i32, =64),
// 2 Wih1(2048x1), 3 Whh1(2048x512), 4 bih1(2048), 5 bhh1(2048),
// 6 Wih2(2048x512), 7 Whh2(2048x512), 8 bih2(2048), 9 bhh2(2048),
// 10 Wlin(1x512), 11 blin(1).  output: 64 f32.
// ---------------------------------------------------------------------------
extern "C" void kernel_launch(void* const* d_in, const int* in_sizes, int n_in,
                              void* d_out, int out_size) {
    (void)in_sizes; (void)n_in; (void)out_size;
    const float* input = (const float*)d_in[0];
    const float* Wih1  = (const float*)d_in[2];
    const float* Whh1  = (const float*)d_in[3];
    const float* bih1  = (const float*)d_in[4];
    const float* bhh1  = (const float*)d_in[5];
    const float* Wih2  = (const float*)d_in[6];
    const float* Whh2  = (const float*)d_in[7];
    const float* bih2  = (const float*)d_in[8];
    const float* bhh2  = (const float*)d_in[9];
    const float* Wlin  = (const float*)d_in[10];
    const float* blin  = (const float*)d_in[11];

    lstm_init_kernel<<<1, 256>>>();
    lstm_main_kernel<<<GRID, TPB>>>(input, Wih1, Whh1, bih1, bhh1,
                                    Wih2, Whh2, bih2, bhh2,
                                    Wlin, blin, (float*)d_out);
}

// round 17
// speedup vs baseline: 4.1336x; 4.1336x over previous
#include <cuda_runtime.h>

// ---------------------------------------------------------------------------
// 2-layer LSTM (H=512) encode (T=1024) + AR decode (64 outputs), batch row 255
// only (the reference output depends only on that row).
//
// Persistent kernel, 128 CTAs x 256 threads = 1024 warps, types MIXED per CTA:
//   warps 0..3: type-1 (layer-1 cell), k = 4*bid + w      (Whh1 rows in regs)
//   warps 4..7: type-2 (layer-2 cell), k = 4*bid + (w-4)  (Whh2+Wih2 in regs)
// -> every SMSP runs one type-1 + one type-2 warp: balanced FMA issue.
//
// ENCODE pipelined (layer-2 lags one step): ONE barrier per encode step.
// AR decode: two barriers/step.
//
// Grid barrier v5 (vs R14 best):
//  - Arrival: red.release.gpu.add.u32 to one of 32 aggregation slots
//    (slot = bid & 31; 4 CTAs/slot; each slot on its own 128B line).
//  - Poll: ONE relaxed load per lane (lane == slot), vote vs 4*epoch.
//  - Ordering: final ld.acquire.gpu on the slot (reads same-or-later RMW in
//    the release sequence => synchronizes-with all arrivals). NO
//    fence.acq_rel.gpu -> no CCTL.IVALL L1 flush, no GPU-scope membar per
//    interval. All cross-SM mutable data uses .cg (L2 = coherence point).
// ---------------------------------------------------------------------------

#define GRID   128
#define TPB    256
#define HH     512
#define T_ENC  1024
#define PRED   64
#define NSLOT  32

// ---- persistent device state (reset by init kernel every launch) -----------
__device__ __align__(16) float g_h1[2][HH];
__device__ __align__(16) float g_h2[2][HH];
__device__ __align__(128) unsigned g_slot[NSLOT * 32];   // one 128B line per slot

__global__ void lstm_init_kernel() {
    int i = threadIdx.x;
    for (int j = i; j < HH; j += blockDim.x) {
        g_h1[0][j] = 0.f; g_h1[1][j] = 0.f;
        g_h2[0][j] = 0.f; g_h2[1][j] = 0.f;
    }
    for (int j = i; j < NSLOT * 32; j += blockDim.x) g_slot[j] = 0u;
}

// ---- sync primitives ---------------------------------------------------------
__device__ __forceinline__ void red_release_add(unsigned* p, unsigned v) {
    asm volatile("red.release.gpu.global.add.u32 [%0], %1;"
                 :: "l"(p), "r"(v) : "memory");
}
__device__ __forceinline__ unsigned ld_relaxed(const unsigned* p) {
    unsigned v;
    asm volatile("ld.relaxed.gpu.u32 %0, [%1];" : "=r"(v) : "l"(p) : "memory");
    return v;
}
__device__ __forceinline__ unsigned ld_acquire(const unsigned* p) {
    unsigned v;
    asm volatile("ld.acquire.gpu.u32 %0, [%1];" : "=r"(v) : "l"(p) : "memory");
    return v;
}

// Grid barrier: CTA arrives with one release-reduction into its aggregation
// slot; warp 0 polls (1 relaxed load per lane), votes, then issues a single
// acquire load to establish ordering for the CTA's subsequent .cg loads.
__device__ __forceinline__ void grid_sync(unsigned& ep, int bid) {
    __syncthreads();                        // CTA's h stores issued before arrival
    ep += 1u;
    if (threadIdx.x == 0)
        red_release_add(&g_slot[(bid & (NSLOT - 1)) * 32], 1u);
    if (threadIdx.x < 32) {
        unsigned* p = &g_slot[threadIdx.x * 32];
        const unsigned want = ep * 4u;      // 4 CTAs per slot, monotonic
        bool ok;
        do {
            ok = __all_sync(0xffffffffu, ld_relaxed(p) >= want);
        } while (!ok);
        (void)ld_acquire(p);                // synchronizes-with all releases
    }
    __syncthreads();                        // publish to all warps
}

// ---- math helpers ------------------------------------------------------------
__device__ __forceinline__ float warp_sum(float s) {
#pragma unroll
    for (int o = 16; o; o >>= 1) s += __shfl_xor_sync(0xffffffffu, s, o);
    return s;
}

__device__ __forceinline__ void load_h_cg(const float* buf, float4 h[4], int lane) {
    const float4* b4 = reinterpret_cast<const float4*>(buf);
#pragma unroll
    for (int j = 0; j < 4; j++) h[j] = __ldcg(&b4[lane + 32 * j]);
}

// 4 register-weight row-dots vs h, interleaved butterfly allreduce.
__device__ __forceinline__ void mv4(const float4 w[4][4], const float4 h[4], float s[4]) {
#pragma unroll
    for (int g = 0; g < 4; ++g) {
        float a = 0.f;
#pragma unroll
        for (int j = 0; j < 4; ++j) {
            a = fmaf(w[g][j].x, h[j].x, a);
            a = fmaf(w[g][j].y, h[j].y, a);
            a = fmaf(w[g][j].z, h[j].z, a);
            a = fmaf(w[g][j].w, h[j].w, a);
        }
        s[g] = a;
    }
#pragma unroll
    for (int o = 16; o; o >>= 1)
#pragma unroll
        for (int g = 0; g < 4; ++g) s[g] += __shfl_xor_sync(0xffffffffu, s[g], o);
}

// 8 dots (two matrices x 4 gates), interleaved butterfly allreduce.
__device__ __forceinline__ void mv8(const float4 wa[4][4], const float4 ha[4],
                                    const float4 wb[4][4], const float4 hb[4],
                                    float s[8]) {
#pragma unroll
    for (int g = 0; g < 4; ++g) {
        float a = 0.f, b = 0.f;
#pragma unroll
        for (int j = 0; j < 4; ++j) {
            a = fmaf(wa[g][j].x, ha[j].x, a);
            a = fmaf(wa[g][j].y, ha[j].y, a);
            a = fmaf(wa[g][j].z, ha[j].z, a);
            a = fmaf(wa[g][j].w, ha[j].w, a);
            b = fmaf(wb[g][j].x, hb[j].x, b);
            b = fmaf(wb[g][j].y, hb[j].y, b);
            b = fmaf(wb[g][j].z, hb[j].z, b);
            b = fmaf(wb[g][j].w, hb[j].w, b);
        }
        s[g] = a; s[4 + g] = b;
    }
#pragma unroll
    for (int o = 16; o; o >>= 1)
#pragma unroll
        for (int g = 0; g < 8; ++g) s[g] += __shfl_xor_sync(0xffffffffu, s[g], o);
}

__device__ __forceinline__ float sigf(float x) { return 1.f / (1.f + __expf(-x)); }

__device__ __forceinline__ float cellf(float pi, float pf, float pg, float po, float& c) {
    float i_ = sigf(pi), f_ = sigf(pf), g_ = tanhf(pg), o_ = sigf(po);
    c = f_ * c + i_ * g_;
    return o_ * tanhf(c);
}

// ---- main persistent kernel ----------------------------------------------------
__global__ void __launch_bounds__(TPB, 1) lstm_main_kernel(
    const float* __restrict__ input,
    const float* __restrict__ Wih1, const float* __restrict__ Whh1,
    const float* __restrict__ bih1, const float* __restrict__ bhh1,
    const float* __restrict__ Wih2, const float* __restrict__ Whh2,
    const float* __restrict__ bih2, const float* __restrict__ bhh2,
    const float* __restrict__ Wlin, const float* __restrict__ blin,
    float* __restrict__ out)
{
    const int  lane = threadIdx.x & 31;
    const int  bid  = blockIdx.x;
    const int  wid  = threadIdx.x >> 5;        // 0..7
    const bool is1  = (wid < 4);               // types mixed per CTA (SMSP balance)
    const int  k    = bid * 4 + (wid & 3);     // 0..511 for each type

    // ---- one-time: this warp's weight rows -> REGISTERS ----
    float4 wA[4][4], wB[4][4];
    {
        const float4* WA = reinterpret_cast<const float4*>(is1 ? Whh1 : Whh2);
#pragma unroll
        for (int g = 0; g < 4; ++g) {
            const float4* row = WA + (size_t)(k + 512 * g) * (HH / 4);
#pragma unroll
            for (int j = 0; j < 4; ++j) wA[g][j] = __ldg(&row[lane + 32 * j]);
        }
        if (!is1) {
            const float4* WB = reinterpret_cast<const float4*>(Wih2);
#pragma unroll
            for (int g = 0; g < 4; ++g) {
                const float4* row = WB + (size_t)(k + 512 * g) * (HH / 4);
#pragma unroll
                for (int j = 0; j < 4; ++j) wB[g][j] = __ldg(&row[lane + 32 * j]);
            }
        } else {
#pragma unroll
            for (int g = 0; g < 4; ++g)
#pragma unroll
                for (int j = 0; j < 4; ++j) wB[g][j] = make_float4(0.f, 0.f, 0.f, 0.f);
        }
    }
    float4 wlin4[4];
    {
        const float4* WL = reinterpret_cast<const float4*>(Wlin);
#pragma unroll
        for (int j = 0; j < 4; ++j) wlin4[j] = __ldg(&WL[lane + 32 * j]);
    }
    float bsum[4], wx[4];
#pragma unroll
    for (int g = 0; g < 4; ++g) {
        int r = k + 512 * g;
        if (is1) { bsum[g] = __ldg(&bih1[r]) + __ldg(&bhh1[r]); wx[g] = __ldg(&Wih1[r]); }
        else     { bsum[g] = __ldg(&bih2[r]) + __ldg(&bhh2[r]); wx[g] = 0.f; }
    }
    const float blin0 = __ldg(blin);

    float cs = 0.f;          // c1 (type-1) or c2 (type-2), lane 0 of this warp
    unsigned ep = 0u;

    // ================= ENCODE: pipelined, ONE barrier per step =================
    // interval t: type-1 computes h1[t]; type-2 computes h2[t-1].
    for (int t = 0; t < T_ENC; ++t) {
        if (is1) {
            float x = __ldg(&input[255 * T_ENC + t]);
            float4 hr[4];
            load_h_cg(g_h1[t & 1], hr, lane);              // h1[t-1]
            float s[4];
            mv4(wA, hr, s);
            if (lane == 0) {
                float h = cellf(s[0] + bsum[0] + wx[0] * x,
                                s[1] + bsum[1] + wx[1] * x,
                                s[2] + bsum[2] + wx[2] * x,
                                s[3] + bsum[3] + wx[3] * x, cs);
                __stcg(&g_h1[(t + 1) & 1][k], h);          // h1[t]
            }
        } else if (t >= 1) {
            float4 h1r[4], h2r[4];
            load_h_cg(g_h1[t & 1], h1r, lane);             // h1[t-1]
            load_h_cg(g_h2[(t - 1) & 1], h2r, lane);       // h2[t-2]
            float s[8];
            mv8(wA, h2r, wB, h1r, s);                      // Whh2 dots, Wih2 dots
            if (lane == 0) {
                float h = cellf(s[0] + s[4] + bsum[0],
                                s[1] + s[5] + bsum[1],
                                s[2] + s[6] + bsum[2],
                                s[3] + s[7] + bsum[3], cs);
                __stcg(&g_h2[t & 1][k], h);                // h2[t-1]
            }
        }
        grid_sync(ep, bid);
    }

    // ================= DRAIN: compute h2[1023] =================
    if (!is1) {
        float4 h1r[4], h2r[4];
        load_h_cg(g_h1[T_ENC & 1], h1r, lane);             // h1[1023]
        load_h_cg(g_h2[(T_ENC - 1) & 1], h2r, lane);       // h2[1022]
        float s[8];
        mv8(wA, h2r, wB, h1r, s);
        if (lane == 0) {
            float h = cellf(s[0] + s[4] + bsum[0],
                            s[1] + s[5] + bsum[1],
                            s[2] + s[6] + bsum[2],
                            s[3] + s[7] + bsum[3], cs);
            __stcg(&g_h2[T_ENC & 1][k], h);                // h2[1023]
        }
    }
    grid_sync(ep, bid);

    // ================= AR DECODE: t = 1024 .. 1086, two barriers/step ==========
    for (int t = T_ENC; t < T_ENC + PRED - 1; ++t) {
        float sA[4];
        if (is1) {
            // y(t-1) = Wlin . h2[t-1] + blin   (h2[t-1] in g_h2[t&1])
            float4 h2r[4];
            load_h_cg(g_h2[t & 1], h2r, lane);
            float y = 0.f;
#pragma unroll
            for (int j = 0; j < 4; ++j) {
                y = fmaf(wlin4[j].x, h2r[j].x, y);
                y = fmaf(wlin4[j].y, h2r[j].y, y);
                y = fmaf(wlin4[j].z, h2r[j].z, y);
                y = fmaf(wlin4[j].w, h2r[j].w, y);
            }
            y = warp_sum(y) + blin0;
            if (k == 0 && lane == 0) out[t - T_ENC] = y;   // out[0..62]
            float x = y;   // bitwise identical in all type-1 warps
            float4 hr[4];
            load_h_cg(g_h1[t & 1], hr, lane);              // h1[t-1]
            float s[4];
            mv4(wA, hr, s);
            if (lane == 0) {
                float h = cellf(s[0] + bsum[0] + wx[0] * x,
                                s[1] + bsum[1] + wx[1] * x,
                                s[2] + bsum[2] + wx[2] * x,
                                s[3] + bsum[3] + wx[3] * x, cs);
                __stcg(&g_h1[(t + 1) & 1][k], h);          // h1[t]
            }
        } else {
            float4 h2r[4];
            load_h_cg(g_h2[t & 1], h2r, lane);             // h2[t-1]
            mv4(wA, h2r, sA);                              // Whh2 partials stay in regs
        }
        grid_sync(ep, bid);

        if (!is1) {
            float4 h1r[4];
            load_h_cg(g_h1[(t + 1) & 1], h1r, lane);       // h1[t]
            float s[4];
            mv4(wB, h1r, s);
            if (lane == 0) {
                float h = cellf(sA[0] + s[0] + bsum[0],
                                sA[1] + s[1] + bsum[1],
                                sA[2] + s[2] + bsum[2],
                                sA[3] + s[3] + bsum[3], cs);
                __stcg(&g_h2[(t + 1) & 1][k], h);          // h2[t]
            }
        }
        grid_sync(ep, bid);
    }

    // ================= EPILOGUE: out[63] = Wlin . h2[1086] + blin ==============
    if (bid == 0 && wid == 0) {
        float4 h2r[4];
        load_h_cg(g_h2[(T_ENC + PRED - 1) & 1], h2r, lane); // h2[1086]
        float y = 0.f;
#pragma unroll
        for (int j = 0; j < 4; ++j) {
            y = fmaf(wlin4[j].x, h2r[j].x, y);
            y = fmaf(wlin4[j].y, h2r[j].y, y);
            y = fmaf(wlin4[j].z, h2r[j].z, y);
            y = fmaf(wlin4[j].w, h2r[j].w, y);
        }
        y = warp_sum(y) + blin0;
        if (lane == 0) out[PRED - 1] = y;
    }
}

// ---------------------------------------------------------------------------
// inputs (metadata order): 0 input(256x1024 f32), 1 pred_len(i32, =64),
// 2 Wih1(2048x1), 3 Whh1(2048x512), 4 bih1(2048), 5 bhh1(2048),
// 6 Wih2(2048x512), 7 Whh2(2048x512), 8 bih2(2048), 9 bhh2(2048),
// 10 Wlin(1x512), 11 blin(1).  output: 64 f32.
// ---------------------------------------------------------------------------
extern "C" void kernel_launch(void* const* d_in, const int* in_sizes, int n_in,
                              void* d_out, int out_size) {
    (void)in_sizes; (void)n_in; (void)out_size;
    const float* input = (const float*)d_in[0];
    const float* Wih1  = (const float*)d_in[2];
    const float* Whh1  = (const float*)d_in[3];
    const float* bih1  = (const float*)d_in[4];
    const float* bhh1  = (const float*)d_in[5];
    const float* Wih2  = (const float*)d_in[6];
    const float* Whh2  = (const float*)d_in[7];
    const float* bih2  = (const float*)d_in[8];
    const float* bhh2  = (const float*)d_in[9];
    const float* Wlin  = (const float*)d_in[10];
    const float* blin  = (const float*)d_in[11];

    lstm_init_kernel<<<1, 256>>>();
    lstm_main_kernel<<<GRID, TPB>>>(input, Wih1, Whh1, bih1, bhh1,
                                    Wih2, Whh2, bih2, bhh2,
                                    Wlin, blin, (float*)d_out);
}